// round 6
// baseline (speedup 1.0000x reference)
#include <cuda_runtime.h>
#include <cuda_bf16.h>

#define B_    8
#define T_    400
#define U_    60
#define U1_   61
#define E_    256
#define H_    512
#define V_    28
#define BLANK_ 27
#define HC_   64
#define NEGF  (-1e30f)
#define LOG2E 1.4426950408889634f
#define LN2   0.6931471805599453f

// Scratch (no cudaMalloc allowed)
__device__ float g_F[B_*T_*H_];        // enc@We + bf   (3200 x 512)
__device__ float g_G[B_*U1_*H_];       // dec@Wd        (488 x 512)
__device__ float g_blank[B_*T_*U1_];   // blank log-probs
__device__ float g_lab[B_*T_*U1_];     // label log-probs (u < 60 valid)

__device__ __forceinline__ float fast_tanh(float x) {
    float y;
    asm("tanh.approx.f32 %0, %1;" : "=f"(y) : "f"(x));
    return y;
}
__device__ __forceinline__ float fast_ex2(float x) {
    float y;
    asm("ex2.approx.f32 %0, %1;" : "=f"(y) : "f"(x));
    return y;
}
__device__ __forceinline__ float fast_lg2(float x) {
    float y;
    asm("lg2.approx.f32 %0, %1;" : "=f"(y) : "f"(x));
    return y;
}

// ---------------------------------------------------------------------------
// Tiled fp32 GEMM: C[M,N] = A[M,K] @ B[K,N] (+ bias[N]).  64x64 tile, 4x4 micro.
// ---------------------------------------------------------------------------
__global__ void gemm_bias_kernel(const float* __restrict__ A,
                                 const float* __restrict__ Bm,
                                 const float* __restrict__ bias,
                                 float* __restrict__ C,
                                 int M, int N, int K)
{
    __shared__ float As[16][65];
    __shared__ float Bs[16][64];
    int tid = threadIdx.x;               // 256 threads
    int tx = tid & 15, ty = tid >> 4;
    int mb = blockIdx.y * 64, nb = blockIdx.x * 64;

    float acc[4][4];
    #pragma unroll
    for (int i = 0; i < 4; i++)
        #pragma unroll
        for (int j = 0; j < 4; j++) acc[i][j] = 0.f;

    for (int k0 = 0; k0 < K; k0 += 16) {
        {
            int r = tid >> 2;
            int q = (tid & 3) << 2;
            float4 av = make_float4(0.f, 0.f, 0.f, 0.f);
            int gm = mb + r;
            if (gm < M) av = *(const float4*)(A + (size_t)gm * K + k0 + q);
            As[q + 0][r] = av.x; As[q + 1][r] = av.y;
            As[q + 2][r] = av.z; As[q + 3][r] = av.w;
        }
        {
            int rk = tid >> 4;
            int qc = (tid & 15) << 2;
            float4 bv = *(const float4*)(Bm + (size_t)(k0 + rk) * N + nb + qc);
            *(float4*)&Bs[rk][qc] = bv;
        }
        __syncthreads();

        #pragma unroll
        for (int kk = 0; kk < 16; kk++) {
            float a0 = As[kk][ty * 4 + 0];
            float a1 = As[kk][ty * 4 + 1];
            float a2 = As[kk][ty * 4 + 2];
            float a3 = As[kk][ty * 4 + 3];
            float4 b4 = *(float4*)&Bs[kk][tx * 4];
            acc[0][0] = fmaf(a0, b4.x, acc[0][0]);
            acc[0][1] = fmaf(a0, b4.y, acc[0][1]);
            acc[0][2] = fmaf(a0, b4.z, acc[0][2]);
            acc[0][3] = fmaf(a0, b4.w, acc[0][3]);
            acc[1][0] = fmaf(a1, b4.x, acc[1][0]);
            acc[1][1] = fmaf(a1, b4.y, acc[1][1]);
            acc[1][2] = fmaf(a1, b4.z, acc[1][2]);
            acc[1][3] = fmaf(a1, b4.w, acc[1][3]);
            acc[2][0] = fmaf(a2, b4.x, acc[2][0]);
            acc[2][1] = fmaf(a2, b4.y, acc[2][1]);
            acc[2][2] = fmaf(a2, b4.z, acc[2][2]);
            acc[2][3] = fmaf(a2, b4.w, acc[2][3]);
            acc[3][0] = fmaf(a3, b4.x, acc[3][0]);
            acc[3][1] = fmaf(a3, b4.y, acc[3][1]);
            acc[3][2] = fmaf(a3, b4.z, acc[3][2]);
            acc[3][3] = fmaf(a3, b4.w, acc[3][3]);
        }
        __syncthreads();
    }

    #pragma unroll
    for (int i = 0; i < 4; i++) {
        int gm = mb + ty * 4 + i;
        if (gm < M) {
            #pragma unroll
            for (int j = 0; j < 4; j++) {
                int gn = nb + tx * 4 + j;
                float bb = bias ? bias[gn] : 0.f;
                C[(size_t)gm * N + gn] = acc[i][j] + bb;
            }
        }
    }
}

// ---------------------------------------------------------------------------
// Fused joint kernel — R2 configuration (fastest measured): scalar FMAs,
// 1 t-row per thread, block (64,4) covers 4 t-rows x 61 u, grid (100, 8).
// ---------------------------------------------------------------------------
__global__ void __launch_bounds__(256)
joint_kernel(const float* __restrict__ Wp,
             const float* __restrict__ bp,
             const int*  __restrict__ targets)
{
    __shared__ float Fs[4][HC_];
    __shared__ float Gs[U1_][HC_ + 4];
    __shared__ float Ws[V_][HC_ + 4];     // Wp transposed: Ws[v][h]
    __shared__ float bps[V_];

    int b  = blockIdx.y;
    int t0 = blockIdx.x * 4;
    int u  = threadIdx.x;                 // 0..63 (active < 61)
    int tl = threadIdx.y;                 // 0..3
    int tid = tl * 64 + u;                // 0..255

    if (tid < V_) bps[tid] = bp[tid];

    const float* Fb = g_F + (size_t)(b * T_ + t0) * H_;
    const float* Gb = g_G + (size_t)b * U1_ * H_;

    float acc[V_];
    #pragma unroll
    for (int v = 0; v < V_; v++) acc[v] = 0.f;

    for (int hc = 0; hc < H_; hc += HC_) {
        // F chunk: 4 x 64 (one element per thread)
        Fs[tid >> 6][tid & 63] = Fb[(size_t)(tid >> 6) * H_ + hc + (tid & 63)];
        // G chunk: 61 x 64 via float4
        for (int i = tid; i < U1_ * (HC_ / 4); i += 256) {
            int r = i / (HC_ / 4);
            int c = (i % (HC_ / 4)) * 4;
            float4 v4 = *(const float4*)(Gb + (size_t)r * H_ + hc + c);
            *(float4*)&Gs[r][c] = v4;
        }
        // Wp^T chunk: 28 x 64
        for (int i = tid; i < V_ * HC_; i += 256) {
            int v = i >> 6;
            int h = i & 63;
            Ws[v][h] = Wp[(size_t)(hc + h) * V_ + v];
        }
        __syncthreads();

        if (u < U1_) {
            #pragma unroll 2
            for (int h = 0; h < HC_; h += 4) {
                float4 f4 = *(const float4*)&Fs[tl][h];
                float4 g4 = *(const float4*)&Gs[u][h];
                float h0 = fast_tanh(f4.x + g4.x);
                float h1 = fast_tanh(f4.y + g4.y);
                float h2 = fast_tanh(f4.z + g4.z);
                float h3 = fast_tanh(f4.w + g4.w);
                #pragma unroll
                for (int v = 0; v < V_; v++) {
                    float4 w = *(const float4*)&Ws[v][h];
                    float s = fmaf(h0, w.x, acc[v]);
                    s = fmaf(h1, w.y, s);
                    s = fmaf(h2, w.z, s);
                    acc[v] = fmaf(h3, w.w, s);
                }
            }
        }
        __syncthreads();
    }

    if (u < U1_) {
        int t = t0 + tl;
        int tgt = (u < U_) ? targets[b * U_ + u] : 0;

        float m = -1e30f;
        #pragma unroll
        for (int v = 0; v < V_; v++) {
            acc[v] += bps[v];
            m = fmaxf(m, acc[v]);
        }
        float s = 0.f;
        #pragma unroll
        for (int v = 0; v < V_; v++) s += fast_ex2((acc[v] - m) * LOG2E);
        float lse = m + fast_lg2(s) * LN2;

        float lv = acc[0];
        #pragma unroll
        for (int v = 1; v < V_; v++)
            if (v == tgt) lv = acc[v];

        size_t idx = (size_t)(b * T_ + t) * U1_ + u;
        g_blank[idx] = acc[BLANK_] - lse;
        if (u < U_) g_lab[idx] = lv - lse;
    }
}

// ---------------------------------------------------------------------------
// Forward DP, branchless wavefront in log2 domain. One block per batch.
// 1024 threads stage lp tables (scaled by log2e) into smem; warp 0 runs the
// 459-step recurrence with shfl neighbor exchange and incremental addressing.
// ---------------------------------------------------------------------------
__global__ void dp_kernel(const int* __restrict__ t_lens,
                          const int* __restrict__ u_lens,
                          float* __restrict__ out)
{
    extern __shared__ float sm[];
    float* sB = sm;                      // T_*U1_   (log2 domain)
    float* sL = sm + T_ * U1_;           // T_*U1_

    int b   = blockIdx.x;
    int tid = threadIdx.x;               // 1024

    const float4* srcB = (const float4*)(g_blank + (size_t)b * T_ * U1_);
    const float4* srcL = (const float4*)(g_lab   + (size_t)b * T_ * U1_);
    const int n4 = T_ * U1_ / 4;         // 6100
    for (int i = tid; i < n4; i += 1024) {
        float4 vb = srcB[i];
        float4 vl = srcL[i];
        vb.x *= LOG2E; vb.y *= LOG2E; vb.z *= LOG2E; vb.w *= LOG2E;
        vl.x *= LOG2E; vl.y *= LOG2E; vl.z *= LOG2E; vl.w *= LOG2E;
        ((float4*)sB)[i] = vb;
        ((float4*)sL)[i] = vl;
    }
    __syncthreads();
    if (tid >= 32) return;

    const int lane = tid;
    const int Tl = t_lens[b], Ul = u_lens[b];
    const int dcap = (Tl - 1) + Ul;
    const bool cap_lo = (Ul < 32) && (lane == Ul);
    const bool cap_hi = (Ul >= 32) && (lane == Ul - 32);

    const int u_lo = lane;                         // 0..31
    const int u_hi = lane + 32;                    // 32..63
    const int ulo_m1 = max(u_lo - 1, 0);
    const int uhi_c  = min(u_hi, U1_ - 1);
    const int uhi_m1 = min(u_hi - 1, U1_ - 1);

    float a_lo = (lane == 0) ? 0.f : NEGF;
    float a_hi = NEGF;
    float res  = 0.f;

    // Incremental row offsets (clamped to [0, T_-1] rows by saturating adds).
    // row(t) offsets: advance by U1_ per step once t enters [0, T_-1].
    #pragma unroll 2
    for (int d = 1; d <= (T_ - 1) + (U1_ - 1); d++) {
        float p_lo = __shfl_up_sync(0xffffffffu, a_lo, 1);
        float p_hi = __shfl_up_sync(0xffffffffu, a_hi, 1);
        float lo31 = __shfl_sync(0xffffffffu, a_lo, 31);
        p_lo = (lane == 0) ? NEGF : p_lo;
        p_hi = (lane == 0) ? lo31 : p_hi;

        // lo cell: u = u_lo, t = d - u_lo
        int t  = d - u_lo;
        int i1 = min(max(t - 1, 0), T_ - 1);
        int i2 = min(max(t, 0), T_ - 1);
        float v1 = a_lo + sB[i1 * U1_ + u_lo];
        float v2 = p_lo + sL[i2 * U1_ + ulo_m1];
        float mx = fmaxf(v1, v2), mn = fminf(v1, v2);
        float n_lo = mx + fast_lg2(1.f + fast_ex2(mn - mx));

        // hi cell: u = u_hi, t = d - u_hi
        int th = d - u_hi;
        int j1 = min(max(th - 1, 0), T_ - 1);
        int j2 = min(max(th, 0), T_ - 1);
        float w1 = a_hi + sB[j1 * U1_ + uhi_c];
        float w2 = p_hi + sL[j2 * U1_ + uhi_m1];
        float mxh = fmaxf(w1, w2), mnh = fminf(w1, w2);
        float n_hi = mxh + fast_lg2(1.f + fast_ex2(mnh - mxh));

        bool hit = (d == dcap);
        res = (hit && cap_lo) ? n_lo : res;
        res = (hit && cap_hi) ? n_hi : res;
        a_lo = n_lo;
        a_hi = n_hi;
    }

    if (cap_lo || cap_hi) {
        float blank_fin = g_blank[(size_t)b * T_ * U1_ + (size_t)(Tl - 1) * U1_ + Ul];
        out[b] = -(res * LN2 + blank_fin);
    }
}

// ---------------------------------------------------------------------------
extern "C" void kernel_launch(void* const* d_in, const int* in_sizes, int n_in,
                              void* d_out, int out_size)
{
    const float* enc     = (const float*)d_in[0];
    const float* dec     = (const float*)d_in[1];
    const float* We      = (const float*)d_in[2];
    const float* Wd      = (const float*)d_in[3];
    const float* bf      = (const float*)d_in[4];
    const float* Wp      = (const float*)d_in[5];
    const float* bp      = (const float*)d_in[6];
    const int*   targets = (const int*)d_in[7];
    const int*   t_lens  = (const int*)d_in[8];
    const int*   u_lens  = (const int*)d_in[9];
    float* out = (float*)d_out;

    float *pF = nullptr, *pG = nullptr;
    cudaGetSymbolAddress((void**)&pF, g_F);
    cudaGetSymbolAddress((void**)&pG, g_G);

    static bool attr_set = false;
    const int dp_smem = 2 * T_ * U1_ * sizeof(float);   // 195200 B
    if (!attr_set) {
        cudaFuncSetAttribute(dp_kernel,
                             cudaFuncAttributeMaxDynamicSharedMemorySize, dp_smem);
        attr_set = true;
    }

    gemm_bias_kernel<<<dim3(H_ / 64, (B_ * T_ + 63) / 64), 256>>>(
        enc, We, bf, pF, B_ * T_, H_, E_);
    gemm_bias_kernel<<<dim3(H_ / 64, (B_ * U1_ + 63) / 64), 256>>>(
        dec, Wd, nullptr, pG, B_ * U1_, H_, E_);
    joint_kernel<<<dim3(T_ / 4, B_), dim3(64, 4)>>>(Wp, bp, targets);
    dp_kernel<<<B_, 1024, dp_smem>>>(t_lens, u_lens, out);
}

// round 7
// speedup vs baseline: 1.2038x; 1.2038x over previous
#include <cuda_runtime.h>
#include <cuda_bf16.h>

#define B_    8
#define T_    400
#define U_    60
#define U1_   61
#define E_    256
#define H_    512
#define V_    28
#define VP_   14
#define BLANK_ 27
#define NEGF  (-1e30f)
#define LOG2E 1.4426950408889634f
#define LN2   0.6931471805599453f

#define GSTR  516                      // padded G row stride (floats)
// smem layout (bytes): G [61*516*4 = 125904] | Ws2 [512*14*8 = 57344] |
//                      F [8*512*4 = 16384]   | bps [112]
#define SM_G   0
#define SM_W   125904
#define SM_F   (125904 + 57344)
#define SM_BP  (SM_F + 16384)
#define JSMEM  (SM_BP + 128)

// Scratch (no cudaMalloc allowed)
__device__ float g_F[B_*T_*H_];
__device__ float g_G[B_*U1_*H_];
__device__ float g_blank[B_*T_*U1_];
__device__ float g_lab[B_*T_*U1_];

__device__ __forceinline__ float fast_tanh(float x) {
    float y; asm("tanh.approx.f32 %0, %1;" : "=f"(y) : "f"(x)); return y;
}
__device__ __forceinline__ float fast_ex2(float x) {
    float y; asm("ex2.approx.f32 %0, %1;" : "=f"(y) : "f"(x)); return y;
}
__device__ __forceinline__ float fast_lg2(float x) {
    float y; asm("lg2.approx.f32 %0, %1;" : "=f"(y) : "f"(x)); return y;
}
__device__ __forceinline__ unsigned long long pack2(float x, float y) {
    unsigned long long r;
    asm("mov.b64 %0, {%1, %2};" : "=l"(r) : "f"(x), "f"(y));
    return r;
}
__device__ __forceinline__ void unpack2(unsigned long long v, float& x, float& y) {
    asm("mov.b64 {%0, %1}, %2;" : "=f"(x), "=f"(y) : "l"(v));
}
__device__ __forceinline__ unsigned long long fma2(unsigned long long a,
                                                   unsigned long long b,
                                                   unsigned long long c) {
    unsigned long long d;
    asm("fma.rn.f32x2 %0, %1, %2, %3;" : "=l"(d) : "l"(a), "l"(b), "l"(c));
    return d;
}

// ---------------------------------------------------------------------------
// Tiled fp32 GEMM: C[M,N] = A[M,K] @ B[K,N] (+ bias[N]).
// ---------------------------------------------------------------------------
__global__ void gemm_bias_kernel(const float* __restrict__ A,
                                 const float* __restrict__ Bm,
                                 const float* __restrict__ bias,
                                 float* __restrict__ C,
                                 int M, int N, int K)
{
    __shared__ float As[16][65];
    __shared__ float Bs[16][64];
    int tid = threadIdx.x;
    int tx = tid & 15, ty = tid >> 4;
    int mb = blockIdx.y * 64, nb = blockIdx.x * 64;

    float acc[4][4];
    #pragma unroll
    for (int i = 0; i < 4; i++)
        #pragma unroll
        for (int j = 0; j < 4; j++) acc[i][j] = 0.f;

    for (int k0 = 0; k0 < K; k0 += 16) {
        {
            int r = tid >> 2;
            int q = (tid & 3) << 2;
            float4 av = make_float4(0.f, 0.f, 0.f, 0.f);
            int gm = mb + r;
            if (gm < M) av = *(const float4*)(A + (size_t)gm * K + k0 + q);
            As[q + 0][r] = av.x; As[q + 1][r] = av.y;
            As[q + 2][r] = av.z; As[q + 3][r] = av.w;
        }
        {
            int rk = tid >> 4;
            int qc = (tid & 15) << 2;
            float4 bv = *(const float4*)(Bm + (size_t)(k0 + rk) * N + nb + qc);
            *(float4*)&Bs[rk][qc] = bv;
        }
        __syncthreads();

        #pragma unroll
        for (int kk = 0; kk < 16; kk++) {
            float a0 = As[kk][ty * 4 + 0];
            float a1 = As[kk][ty * 4 + 1];
            float a2 = As[kk][ty * 4 + 2];
            float a3 = As[kk][ty * 4 + 3];
            float4 b4 = *(float4*)&Bs[kk][tx * 4];
            acc[0][0] = fmaf(a0, b4.x, acc[0][0]);
            acc[0][1] = fmaf(a0, b4.y, acc[0][1]);
            acc[0][2] = fmaf(a0, b4.z, acc[0][2]);
            acc[0][3] = fmaf(a0, b4.w, acc[0][3]);
            acc[1][0] = fmaf(a1, b4.x, acc[1][0]);
            acc[1][1] = fmaf(a1, b4.y, acc[1][1]);
            acc[1][2] = fmaf(a1, b4.z, acc[1][2]);
            acc[1][3] = fmaf(a1, b4.w, acc[1][3]);
            acc[2][0] = fmaf(a2, b4.x, acc[2][0]);
            acc[2][1] = fmaf(a2, b4.y, acc[2][1]);
            acc[2][2] = fmaf(a2, b4.z, acc[2][2]);
            acc[2][3] = fmaf(a2, b4.w, acc[2][3]);
            acc[3][0] = fmaf(a3, b4.x, acc[3][0]);
            acc[3][1] = fmaf(a3, b4.y, acc[3][1]);
            acc[3][2] = fmaf(a3, b4.z, acc[3][2]);
            acc[3][3] = fmaf(a3, b4.w, acc[3][3]);
        }
        __syncthreads();
    }

    #pragma unroll
    for (int i = 0; i < 4; i++) {
        int gm = mb + ty * 4 + i;
        if (gm < M) {
            #pragma unroll
            for (int j = 0; j < 4; j++) {
                int gn = nb + tx * 4 + j;
                float bb = bias ? bias[gn] : 0.f;
                C[(size_t)gm * N + gn] = acc[i][j] + bb;
            }
        }
    }
}

// ---------------------------------------------------------------------------
// Fused joint kernel: f32x2 FMA, 4 t-rows/thread, ONE-SHOT smem residency.
// Block (64,2)=128 thr covers 8 t-rows x 61 u. All of G[b] (61x512), packed
// Wp (512x14 pairs), F tile (8x512) staged once; single barrier; then a
// barrier-free 128-step FMA2 mainloop.
// ---------------------------------------------------------------------------
__global__ void __launch_bounds__(128)
joint_kernel(const float* __restrict__ Wp,
             const float* __restrict__ bp,
             const int*  __restrict__ targets)
{
    extern __shared__ char smraw[];
    float*              sG  = (float*)(smraw + SM_G);
    unsigned long long* sW  = (unsigned long long*)(smraw + SM_W);
    float*              sF  = (float*)(smraw + SM_F);
    float*              sBp = (float*)(smraw + SM_BP);

    int b  = blockIdx.y;
    int t0 = blockIdx.x * 8;
    int u  = threadIdx.x;                 // 0..63 (active < 61)
    int tl = threadIdx.y;                 // 0..1
    int tid = tl * 64 + u;                // 0..127

    const float* Fb = g_F + (size_t)(b * T_ + t0) * H_;
    const float* Gb = g_G + (size_t)b * U1_ * H_;

    if (tid < V_) sBp[tid] = bp[tid];
    // G: 61 rows x 512 -> padded stride 516
    for (int i = tid; i < U1_ * (H_ / 4); i += 128) {
        int r = i >> 7;                   // H_/4 = 128
        int c = (i & 127) << 2;
        float4 v4 = *(const float4*)(Gb + (size_t)r * H_ + c);
        *(float4*)&sG[r * GSTR + c] = v4;
    }
    // Wp packed pairs: [h][p]
    for (int i = tid; i < H_ * VP_; i += 128) {
        int h = i / VP_;
        int p = i - h * VP_;
        float2 w = *(const float2*)(Wp + (size_t)h * V_ + 2 * p);
        sW[h * VP_ + p] = pack2(w.x, w.y);
    }
    // F: 8 rows x 512
    for (int i = tid; i < 8 * (H_ / 4); i += 128) {
        int r = i >> 7;
        int c = (i & 127) << 2;
        *(float4*)&sF[r * H_ + c] = *(const float4*)(Fb + (size_t)r * H_ + c);
    }
    __syncthreads();

    unsigned long long acc2[4][VP_];
    #pragma unroll
    for (int r = 0; r < 4; r++)
        #pragma unroll
        for (int p = 0; p < VP_; p++) acc2[r][p] = 0ull;

    if (u < U1_) {
        const float* sGu = sG + u * GSTR;
        const float* sF0 = sF + (tl)     * H_;
        const float* sF1 = sF + (tl + 2) * H_;
        const float* sF2 = sF + (tl + 4) * H_;
        const float* sF3 = sF + (tl + 6) * H_;
        #pragma unroll 1
        for (int h = 0; h < H_; h += 4) {
            float4 g4 = *(const float4*)(sGu + h);
            float4 f0 = *(const float4*)(sF0 + h);
            float4 f1 = *(const float4*)(sF1 + h);
            float4 f2 = *(const float4*)(sF2 + h);
            float4 f3 = *(const float4*)(sF3 + h);
            #pragma unroll
            for (int j = 0; j < 4; j++) {
                float gj  = (j == 0) ? g4.x : (j == 1) ? g4.y : (j == 2) ? g4.z : g4.w;
                float a0j = (j == 0) ? f0.x : (j == 1) ? f0.y : (j == 2) ? f0.z : f0.w;
                float a1j = (j == 0) ? f1.x : (j == 1) ? f1.y : (j == 2) ? f1.z : f1.w;
                float a2j = (j == 0) ? f2.x : (j == 1) ? f2.y : (j == 2) ? f2.z : f2.w;
                float a3j = (j == 0) ? f3.x : (j == 1) ? f3.y : (j == 2) ? f3.z : f3.w;
                float t0v = fast_tanh(a0j + gj);
                float t1v = fast_tanh(a1j + gj);
                float t2v = fast_tanh(a2j + gj);
                float t3v = fast_tanh(a3j + gj);
                unsigned long long h0 = pack2(t0v, t0v);
                unsigned long long h1 = pack2(t1v, t1v);
                unsigned long long h2 = pack2(t2v, t2v);
                unsigned long long h3 = pack2(t3v, t3v);
                const unsigned long long* wrow = sW + (h + j) * VP_;
                #pragma unroll
                for (int p = 0; p < VP_; p++) {
                    unsigned long long w = wrow[p];
                    acc2[0][p] = fma2(h0, w, acc2[0][p]);
                    acc2[1][p] = fma2(h1, w, acc2[1][p]);
                    acc2[2][p] = fma2(h2, w, acc2[2][p]);
                    acc2[3][p] = fma2(h3, w, acc2[3][p]);
                }
            }
        }

        int tgt = (u < U_) ? targets[b * U_ + u] : 0;
        #pragma unroll
        for (int r = 0; r < 4; r++) {
            int t = t0 + tl + 2 * r;
            float logits[V_];
            #pragma unroll
            for (int p = 0; p < VP_; p++)
                unpack2(acc2[r][p], logits[2 * p], logits[2 * p + 1]);

            float m = -1e30f;
            #pragma unroll
            for (int v = 0; v < V_; v++) {
                logits[v] += sBp[v];
                m = fmaxf(m, logits[v]);
            }
            float s = 0.f;
            #pragma unroll
            for (int v = 0; v < V_; v++) s += fast_ex2((logits[v] - m) * LOG2E);
            float lse = m + fast_lg2(s) * LN2;

            float lv = logits[0];
            #pragma unroll
            for (int v = 1; v < V_; v++)
                if (v == tgt) lv = logits[v];

            size_t idx = (size_t)(b * T_ + t) * U1_ + u;
            g_blank[idx] = logits[BLANK_] - lse;
            if (u < U_) g_lab[idx] = lv - lse;
        }
    }
}

// ---------------------------------------------------------------------------
// Forward DP, branchless wavefront in log2 domain (unchanged, 42us).
// ---------------------------------------------------------------------------
__global__ void dp_kernel(const int* __restrict__ t_lens,
                          const int* __restrict__ u_lens,
                          float* __restrict__ out)
{
    extern __shared__ float sm[];
    float* sB = sm;
    float* sL = sm + T_ * U1_;

    int b   = blockIdx.x;
    int tid = threadIdx.x;

    const float4* srcB = (const float4*)(g_blank + (size_t)b * T_ * U1_);
    const float4* srcL = (const float4*)(g_lab   + (size_t)b * T_ * U1_);
    const int n4 = T_ * U1_ / 4;
    for (int i = tid; i < n4; i += 1024) {
        float4 vb = srcB[i];
        float4 vl = srcL[i];
        vb.x *= LOG2E; vb.y *= LOG2E; vb.z *= LOG2E; vb.w *= LOG2E;
        vl.x *= LOG2E; vl.y *= LOG2E; vl.z *= LOG2E; vl.w *= LOG2E;
        ((float4*)sB)[i] = vb;
        ((float4*)sL)[i] = vl;
    }
    __syncthreads();
    if (tid >= 32) return;

    const int lane = tid;
    const int Tl = t_lens[b], Ul = u_lens[b];
    const int dcap = (Tl - 1) + Ul;
    const bool cap_lo = (Ul < 32) && (lane == Ul);
    const bool cap_hi = (Ul >= 32) && (lane == Ul - 32);

    const int u_lo = lane;
    const int u_hi = lane + 32;
    const int ulo_m1 = max(u_lo - 1, 0);
    const int uhi_c  = min(u_hi, U1_ - 1);
    const int uhi_m1 = min(u_hi - 1, U1_ - 1);

    float a_lo = (lane == 0) ? 0.f : NEGF;
    float a_hi = NEGF;
    float res  = 0.f;

    #pragma unroll 2
    for (int d = 1; d <= (T_ - 1) + (U1_ - 1); d++) {
        float p_lo = __shfl_up_sync(0xffffffffu, a_lo, 1);
        float p_hi = __shfl_up_sync(0xffffffffu, a_hi, 1);
        float lo31 = __shfl_sync(0xffffffffu, a_lo, 31);
        p_lo = (lane == 0) ? NEGF : p_lo;
        p_hi = (lane == 0) ? lo31 : p_hi;

        int t  = d - u_lo;
        int i1 = min(max(t - 1, 0), T_ - 1);
        int i2 = min(max(t, 0), T_ - 1);
        float v1 = a_lo + sB[i1 * U1_ + u_lo];
        float v2 = p_lo + sL[i2 * U1_ + ulo_m1];
        float mx = fmaxf(v1, v2), mn = fminf(v1, v2);
        float n_lo = mx + fast_lg2(1.f + fast_ex2(mn - mx));

        int th = d - u_hi;
        int j1 = min(max(th - 1, 0), T_ - 1);
        int j2 = min(max(th, 0), T_ - 1);
        float w1 = a_hi + sB[j1 * U1_ + uhi_c];
        float w2 = p_hi + sL[j2 * U1_ + uhi_m1];
        float mxh = fmaxf(w1, w2), mnh = fminf(w1, w2);
        float n_hi = mxh + fast_lg2(1.f + fast_ex2(mnh - mxh));

        bool hit = (d == dcap);
        res = (hit && cap_lo) ? n_lo : res;
        res = (hit && cap_hi) ? n_hi : res;
        a_lo = n_lo;
        a_hi = n_hi;
    }

    if (cap_lo || cap_hi) {
        float blank_fin = g_blank[(size_t)b * T_ * U1_ + (size_t)(Tl - 1) * U1_ + Ul];
        out[b] = -(res * LN2 + blank_fin);
    }
}

// ---------------------------------------------------------------------------
extern "C" void kernel_launch(void* const* d_in, const int* in_sizes, int n_in,
                              void* d_out, int out_size)
{
    const float* enc     = (const float*)d_in[0];
    const float* dec     = (const float*)d_in[1];
    const float* We      = (const float*)d_in[2];
    const float* Wd      = (const float*)d_in[3];
    const float* bf      = (const float*)d_in[4];
    const float* Wp      = (const float*)d_in[5];
    const float* bp      = (const float*)d_in[6];
    const int*   targets = (const int*)d_in[7];
    const int*   t_lens  = (const int*)d_in[8];
    const int*   u_lens  = (const int*)d_in[9];
    float* out = (float*)d_out;

    float *pF = nullptr, *pG = nullptr;
    cudaGetSymbolAddress((void**)&pF, g_F);
    cudaGetSymbolAddress((void**)&pG, g_G);

    static bool attr_set = false;
    const int dp_smem = 2 * T_ * U1_ * sizeof(float);
    if (!attr_set) {
        cudaFuncSetAttribute(dp_kernel,
                             cudaFuncAttributeMaxDynamicSharedMemorySize, dp_smem);
        cudaFuncSetAttribute(joint_kernel,
                             cudaFuncAttributeMaxDynamicSharedMemorySize, JSMEM);
        attr_set = true;
    }

    gemm_bias_kernel<<<dim3(H_ / 64, (B_ * T_ + 63) / 64), 256>>>(
        enc, We, bf, pF, B_ * T_, H_, E_);
    gemm_bias_kernel<<<dim3(H_ / 64, (B_ * U1_ + 63) / 64), 256>>>(
        dec, Wd, nullptr, pG, B_ * U1_, H_, E_);
    joint_kernel<<<dim3(T_ / 8, B_), dim3(64, 2), JSMEM>>>(Wp, bp, targets);
    dp_kernel<<<B_, 1024, dp_smem>>>(t_lens, u_lens, out);
}

// round 8
// speedup vs baseline: 1.8666x; 1.5507x over previous
#include <cuda_runtime.h>
#include <cuda_bf16.h>
#include <cstdint>

#define B_    8
#define T_    400
#define U_    60
#define U1_   61
#define E_    256
#define H_    512
#define V_    28
#define BLANK_ 27
#define NEGF  (-1e30f)
#define LOG2E 1.4426950408889634f
#define LN2   0.6931471805599453f

// joint smem layout (bytes)
#define GSTR   516                          // G row stride (floats)
#define DSTR   34                           // epilogue D row stride (floats)
#define SM_G   0                            // 64*516*4   = 132096
#define SM_F   132096                       // 8*512*4    = 16384
#define SM_BF  148480                       // 32*4*32*8  = 32768
#define SM_D   181248                       // 8*16*34*4  = 17408
#define SM_BP  198656                       // 128
#define JSMEM  198784

// Scratch (no cudaMalloc allowed)
__device__ float g_F[B_*T_*H_];
__device__ float g_G[B_*U1_*H_];
__device__ float g_blank[B_*T_*U1_];
__device__ float g_lab[B_*T_*U1_];

__device__ __forceinline__ float fast_tanh(float x) {
    float y; asm("tanh.approx.f32 %0, %1;" : "=f"(y) : "f"(x)); return y;
}
__device__ __forceinline__ float fast_ex2(float x) {
    float y; asm("ex2.approx.f32 %0, %1;" : "=f"(y) : "f"(x)); return y;
}
__device__ __forceinline__ float fast_lg2(float x) {
    float y; asm("lg2.approx.f32 %0, %1;" : "=f"(y) : "f"(x)); return y;
}
// pack two f32 into bf16x2: low half = lo, high half = hi
__device__ __forceinline__ uint32_t pack_bf16x2(float lo, float hi) {
    uint32_t r;
    asm("cvt.rn.bf16x2.f32 %0, %1, %2;" : "=r"(r) : "f"(hi), "f"(lo));
    return r;
}
__device__ __forceinline__ void mma_bf16(float& d0, float& d1, float& d2, float& d3,
                                         uint32_t a0, uint32_t a1, uint32_t a2, uint32_t a3,
                                         uint32_t b0, uint32_t b1) {
    asm("mma.sync.aligned.m16n8k16.row.col.f32.bf16.bf16.f32 "
        "{%0,%1,%2,%3}, {%4,%5,%6,%7}, {%8,%9}, {%0,%1,%2,%3};"
        : "+f"(d0), "+f"(d1), "+f"(d2), "+f"(d3)
        : "r"(a0), "r"(a1), "r"(a2), "r"(a3), "r"(b0), "r"(b1));
}

// ---------------------------------------------------------------------------
// Tiled fp32 GEMM: C[M,N] = A[M,K] @ B[K,N] (+ bias[N]).
// ---------------------------------------------------------------------------
__global__ void gemm_bias_kernel(const float* __restrict__ A,
                                 const float* __restrict__ Bm,
                                 const float* __restrict__ bias,
                                 float* __restrict__ C,
                                 int M, int N, int K)
{
    __shared__ float As[16][65];
    __shared__ float Bs[16][64];
    int tid = threadIdx.x;
    int tx = tid & 15, ty = tid >> 4;
    int mb = blockIdx.y * 64, nb = blockIdx.x * 64;

    float acc[4][4];
    #pragma unroll
    for (int i = 0; i < 4; i++)
        #pragma unroll
        for (int j = 0; j < 4; j++) acc[i][j] = 0.f;

    for (int k0 = 0; k0 < K; k0 += 16) {
        {
            int r = tid >> 2;
            int q = (tid & 3) << 2;
            float4 av = make_float4(0.f, 0.f, 0.f, 0.f);
            int gm = mb + r;
            if (gm < M) av = *(const float4*)(A + (size_t)gm * K + k0 + q);
            As[q + 0][r] = av.x; As[q + 1][r] = av.y;
            As[q + 2][r] = av.z; As[q + 3][r] = av.w;
        }
        {
            int rk = tid >> 4;
            int qc = (tid & 15) << 2;
            float4 bv = *(const float4*)(Bm + (size_t)(k0 + rk) * N + nb + qc);
            *(float4*)&Bs[rk][qc] = bv;
        }
        __syncthreads();

        #pragma unroll
        for (int kk = 0; kk < 16; kk++) {
            float a0 = As[kk][ty * 4 + 0];
            float a1 = As[kk][ty * 4 + 1];
            float a2 = As[kk][ty * 4 + 2];
            float a3 = As[kk][ty * 4 + 3];
            float4 b4 = *(float4*)&Bs[kk][tx * 4];
            acc[0][0] = fmaf(a0, b4.x, acc[0][0]);
            acc[0][1] = fmaf(a0, b4.y, acc[0][1]);
            acc[0][2] = fmaf(a0, b4.z, acc[0][2]);
            acc[0][3] = fmaf(a0, b4.w, acc[0][3]);
            acc[1][0] = fmaf(a1, b4.x, acc[1][0]);
            acc[1][1] = fmaf(a1, b4.y, acc[1][1]);
            acc[1][2] = fmaf(a1, b4.z, acc[1][2]);
            acc[1][3] = fmaf(a1, b4.w, acc[1][3]);
            acc[2][0] = fmaf(a2, b4.x, acc[2][0]);
            acc[2][1] = fmaf(a2, b4.y, acc[2][1]);
            acc[2][2] = fmaf(a2, b4.z, acc[2][2]);
            acc[2][3] = fmaf(a2, b4.w, acc[2][3]);
            acc[3][0] = fmaf(a3, b4.x, acc[3][0]);
            acc[3][1] = fmaf(a3, b4.y, acc[3][1]);
            acc[3][2] = fmaf(a3, b4.z, acc[3][2]);
            acc[3][3] = fmaf(a3, b4.w, acc[3][3]);
        }
        __syncthreads();
    }

    #pragma unroll
    for (int i = 0; i < 4; i++) {
        int gm = mb + ty * 4 + i;
        if (gm < M) {
            #pragma unroll
            for (int j = 0; j < 4; j++) {
                int gn = nb + tx * 4 + j;
                float bb = bias ? bias[gn] : 0.f;
                C[(size_t)gm * N + gn] = acc[i][j] + bb;
            }
        }
    }
}

// ---------------------------------------------------------------------------
// HMMA joint kernel. Block = 256 thr (8 warps) covers 8 t-rows x 64 u (padded
// from 61). Warp w: u-strip s = w%4 (u0 = 16s), t-subrange tsub = w/4, looping
// 4 t values. Per k-chunk (16): lanes compute A-fragments of tanh(F+G) in bf16,
// multiply against pre-packed Wp B-fragments (smem), accumulate D in fp32 regs.
// Epilogue per t: D -> smem, 16 lanes do log-softmax, emit blank/label lps.
// ---------------------------------------------------------------------------
__global__ void __launch_bounds__(256)
joint_hmma_kernel(const float* __restrict__ Wp,
                  const float* __restrict__ bp,
                  const int*  __restrict__ targets)
{
    extern __shared__ char smraw[];
    float*    sG  = (float*)(smraw + SM_G);
    float*    sF  = (float*)(smraw + SM_F);
    uint32_t* sBf = (uint32_t*)(smraw + SM_BF);
    float*    sD  = (float*)(smraw + SM_D);
    float*    sBp = (float*)(smraw + SM_BP);

    const int b     = blockIdx.y;
    const int tbase = blockIdx.x * 8;
    const int tid   = threadIdx.x;
    const int wid   = tid >> 5;
    const int lane  = tid & 31;

    const float* Fb = g_F + (size_t)(b * T_ + tbase) * H_;
    const float* Gb = g_G + (size_t)b * U1_ * H_;

    if (tid < V_) sBp[tid] = bp[tid];

    // stage G: 61x512 -> 64x516 (rows 61..63 zero)
    for (int i = tid; i < 64 * (H_ / 4); i += 256) {
        int r = i >> 7;                  // 0..63
        int c = (i & 127) << 2;
        float4 v4 = make_float4(0.f, 0.f, 0.f, 0.f);
        if (r < U1_) v4 = *(const float4*)(Gb + (size_t)r * H_ + c);
        *(float4*)&sG[r * GSTR + c] = v4;
    }
    // stage F: 8 x 512
    for (int i = tid; i < 8 * (H_ / 4); i += 256) {
        int r = i >> 7;
        int c = (i & 127) << 2;
        *(float4*)&sF[r * H_ + c] = *(const float4*)(Fb + (size_t)r * H_ + c);
    }
    // pre-pack Wp B-fragments: [chunk 32][ntile 4][lane 32] x 2 u32
    for (int i = tid; i < 32 * 4 * 32; i += 256) {
        int ch = i >> 7;
        int nt = (i >> 5) & 3;
        int l  = i & 31;
        int kA = ch * 16 + 2 * (l & 3);
        int n  = nt * 8 + (l >> 2);
        uint32_t b0 = 0, b1 = 0;
        if (n < V_) {
            b0 = pack_bf16x2(Wp[(size_t)kA * V_ + n],       Wp[(size_t)(kA + 1) * V_ + n]);
            b1 = pack_bf16x2(Wp[(size_t)(kA + 8) * V_ + n], Wp[(size_t)(kA + 9) * V_ + n]);
        }
        sBf[(size_t)i * 2 + 0] = b0;
        sBf[(size_t)i * 2 + 1] = b1;
    }
    __syncthreads();

    const int s    = wid & 3;            // u strip
    const int tsub = wid >> 2;           // 0/1
    const int u0   = s * 16;
    const int gr    = lane >> 2;
    const int cbase = (lane & 3) * 2;

    const float* gRowA = sG + (u0 + gr) * GSTR;
    const float* gRowB = sG + (u0 + gr + 8) * GSTR;
    float* sDw = sD + wid * (16 * DSTR);

    #pragma unroll 1
    for (int it = 0; it < 4; it++) {
        const int tloc = tsub * 4 + it;
        const float* fRow = sF + tloc * H_;

        float d0[4], d1[4], d2[4], d3[4];
        #pragma unroll
        for (int nt = 0; nt < 4; nt++) { d0[nt] = d1[nt] = d2[nt] = d3[nt] = 0.f; }

        #pragma unroll 2
        for (int ch = 0; ch < 32; ch++) {
            int k = ch * 16 + cbase;
            float2 fA  = *(const float2*)(fRow  + k);
            float2 fB  = *(const float2*)(fRow  + k + 8);
            float2 gAa = *(const float2*)(gRowA + k);
            float2 gBa = *(const float2*)(gRowA + k + 8);
            float2 gAb = *(const float2*)(gRowB + k);
            float2 gBb = *(const float2*)(gRowB + k + 8);
            uint32_t a0 = pack_bf16x2(fast_tanh(fA.x + gAa.x), fast_tanh(fA.y + gAa.y));
            uint32_t a1 = pack_bf16x2(fast_tanh(fA.x + gAb.x), fast_tanh(fA.y + gAb.y));
            uint32_t a2 = pack_bf16x2(fast_tanh(fB.x + gBa.x), fast_tanh(fB.y + gBa.y));
            uint32_t a3 = pack_bf16x2(fast_tanh(fB.x + gBb.x), fast_tanh(fB.y + gBb.y));
            const uint32_t* bf = sBf + (size_t)(ch * 4) * 64 + lane * 2;
            #pragma unroll
            for (int nt = 0; nt < 4; nt++) {
                uint32_t bb0 = bf[nt * 64 + 0];
                uint32_t bb1 = bf[nt * 64 + 1];
                mma_bf16(d0[nt], d1[nt], d2[nt], d3[nt], a0, a1, a2, a3, bb0, bb1);
            }
        }

        // write D frags to smem
        #pragma unroll
        for (int nt = 0; nt < 4; nt++) {
            int c = nt * 8 + cbase;
            *(float2*)&sDw[gr * DSTR + c]       = make_float2(d0[nt], d1[nt]);
            *(float2*)&sDw[(gr + 8) * DSTR + c] = make_float2(d2[nt], d3[nt]);
        }
        __syncwarp();

        if (lane < 16) {
            int u = u0 + lane;
            if (u < U1_) {
                int t = tbase + tloc;
                float logits[V_];
                float m = -1e30f;
                #pragma unroll
                for (int v = 0; v < V_; v++) {
                    logits[v] = sDw[lane * DSTR + v] + sBp[v];
                    m = fmaxf(m, logits[v]);
                }
                float ssum = 0.f;
                #pragma unroll
                for (int v = 0; v < V_; v++) ssum += fast_ex2((logits[v] - m) * LOG2E);
                float lse = m + fast_lg2(ssum) * LN2;

                int tgt = (u < U_) ? targets[b * U_ + u] : 0;
                float lv = logits[0];
                #pragma unroll
                for (int v = 1; v < V_; v++)
                    if (v == tgt) lv = logits[v];

                size_t idx = (size_t)(b * T_ + t) * U1_ + u;
                g_blank[idx] = logits[BLANK_] - lse;
                if (u < U_) g_lab[idx] = lv - lse;
            }
        }
        __syncwarp();
    }
}

// ---------------------------------------------------------------------------
// Forward DP, branchless wavefront in log2 domain (unchanged).
// ---------------------------------------------------------------------------
__global__ void dp_kernel(const int* __restrict__ t_lens,
                          const int* __restrict__ u_lens,
                          float* __restrict__ out)
{
    extern __shared__ float sm[];
    float* sB = sm;
    float* sL = sm + T_ * U1_;

    int b   = blockIdx.x;
    int tid = threadIdx.x;

    const float4* srcB = (const float4*)(g_blank + (size_t)b * T_ * U1_);
    const float4* srcL = (const float4*)(g_lab   + (size_t)b * T_ * U1_);
    const int n4 = T_ * U1_ / 4;
    for (int i = tid; i < n4; i += 1024) {
        float4 vb = srcB[i];
        float4 vl = srcL[i];
        vb.x *= LOG2E; vb.y *= LOG2E; vb.z *= LOG2E; vb.w *= LOG2E;
        vl.x *= LOG2E; vl.y *= LOG2E; vl.z *= LOG2E; vl.w *= LOG2E;
        ((float4*)sB)[i] = vb;
        ((float4*)sL)[i] = vl;
    }
    __syncthreads();
    if (tid >= 32) return;

    const int lane = tid;
    const int Tl = t_lens[b], Ul = u_lens[b];
    const int dcap = (Tl - 1) + Ul;
    const bool cap_lo = (Ul < 32) && (lane == Ul);
    const bool cap_hi = (Ul >= 32) && (lane == Ul - 32);

    const int u_lo = lane;
    const int u_hi = lane + 32;
    const int ulo_m1 = max(u_lo - 1, 0);
    const int uhi_c  = min(u_hi, U1_ - 1);
    const int uhi_m1 = min(u_hi - 1, U1_ - 1);

    float a_lo = (lane == 0) ? 0.f : NEGF;
    float a_hi = NEGF;
    float res  = 0.f;

    #pragma unroll 2
    for (int d = 1; d <= (T_ - 1) + (U1_ - 1); d++) {
        float p_lo = __shfl_up_sync(0xffffffffu, a_lo, 1);
        float p_hi = __shfl_up_sync(0xffffffffu, a_hi, 1);
        float lo31 = __shfl_sync(0xffffffffu, a_lo, 31);
        p_lo = (lane == 0) ? NEGF : p_lo;
        p_hi = (lane == 0) ? lo31 : p_hi;

        int t  = d - u_lo;
        int i1 = min(max(t - 1, 0), T_ - 1);
        int i2 = min(max(t, 0), T_ - 1);
        float v1 = a_lo + sB[i1 * U1_ + u_lo];
        float v2 = p_lo + sL[i2 * U1_ + ulo_m1];
        float mx = fmaxf(v1, v2), mn = fminf(v1, v2);
        float n_lo = mx + fast_lg2(1.f + fast_ex2(mn - mx));

        int th = d - u_hi;
        int j1 = min(max(th - 1, 0), T_ - 1);
        int j2 = min(max(th, 0), T_ - 1);
        float w1 = a_hi + sB[j1 * U1_ + uhi_c];
        float w2 = p_hi + sL[j2 * U1_ + uhi_m1];
        float mxh = fmaxf(w1, w2), mnh = fminf(w1, w2);
        float n_hi = mxh + fast_lg2(1.f + fast_ex2(mnh - mxh));

        bool hit = (d == dcap);
        res = (hit && cap_lo) ? n_lo : res;
        res = (hit && cap_hi) ? n_hi : res;
        a_lo = n_lo;
        a_hi = n_hi;
    }

    if (cap_lo || cap_hi) {
        float blank_fin = g_blank[(size_t)b * T_ * U1_ + (size_t)(Tl - 1) * U1_ + Ul];
        out[b] = -(res * LN2 + blank_fin);
    }
}

// ---------------------------------------------------------------------------
extern "C" void kernel_launch(void* const* d_in, const int* in_sizes, int n_in,
                              void* d_out, int out_size)
{
    const float* enc     = (const float*)d_in[0];
    const float* dec     = (const float*)d_in[1];
    const float* We      = (const float*)d_in[2];
    const float* Wd      = (const float*)d_in[3];
    const float* bf      = (const float*)d_in[4];
    const float* Wp      = (const float*)d_in[5];
    const float* bp      = (const float*)d_in[6];
    const int*   targets = (const int*)d_in[7];
    const int*   t_lens  = (const int*)d_in[8];
    const int*   u_lens  = (const int*)d_in[9];
    float* out = (float*)d_out;

    float *pF = nullptr, *pG = nullptr;
    cudaGetSymbolAddress((void**)&pF, g_F);
    cudaGetSymbolAddress((void**)&pG, g_G);

    static bool attr_set = false;
    const int dp_smem = 2 * T_ * U1_ * sizeof(float);
    if (!attr_set) {
        cudaFuncSetAttribute(dp_kernel,
                             cudaFuncAttributeMaxDynamicSharedMemorySize, dp_smem);
        cudaFuncSetAttribute(joint_hmma_kernel,
                             cudaFuncAttributeMaxDynamicSharedMemorySize, JSMEM);
        attr_set = true;
    }

    gemm_bias_kernel<<<dim3(H_ / 64, (B_ * T_ + 63) / 64), 256>>>(
        enc, We, bf, pF, B_ * T_, H_, E_);
    gemm_bias_kernel<<<dim3(H_ / 64, (B_ * U1_ + 63) / 64), 256>>>(
        dec, Wd, nullptr, pG, B_ * U1_, H_, E_);
    joint_hmma_kernel<<<dim3(T_ / 8, B_), 256, JSMEM>>>(Wp, bp, targets);
    dp_kernel<<<B_, 1024, dp_smem>>>(t_lens, u_lens, out);
}

// round 9
// speedup vs baseline: 2.3315x; 1.2490x over previous
#include <cuda_runtime.h>
#include <cuda_bf16.h>
#include <cstdint>

#define B_    8
#define T_    400
#define U_    60
#define U1_   61
#define E_    256
#define H_    512
#define V_    28
#define BLANK_ 27
#define NEGF  (-1e30f)
#define LOG2E 1.4426950408889634f
#define LN2   0.6931471805599453f

// joint smem layout (bytes)
#define GSTR   516
#define DSTR   34
#define SM_G   0
#define SM_F   132096
#define SM_BF  148480
#define SM_D   181248
#define SM_BP  198656
#define JSMEM  198784

// gemm smem: sA [64][132] u32 + sB [64][132] u32
#define GASTR  132
#define GEMM_SMEM (2 * 64 * GASTR * 4)

// dp smem: 2*T*U1 floats + 128 pad (prefetch overrun)
#define DP_SMEM ((2 * T_ * U1_ + 128) * 4)

// Scratch (no cudaMalloc allowed)
__device__ float g_F[B_*T_*H_];
__device__ float g_G[B_*U1_*H_];
__device__ float g_blank[B_*T_*U1_];
__device__ float g_lab[B_*T_*U1_];

__device__ __forceinline__ float fast_tanh(float x) {
    float y; asm("tanh.approx.f32 %0, %1;" : "=f"(y) : "f"(x)); return y;
}
__device__ __forceinline__ float fast_ex2(float x) {
    float y; asm("ex2.approx.f32 %0, %1;" : "=f"(y) : "f"(x)); return y;
}
__device__ __forceinline__ float fast_lg2(float x) {
    float y; asm("lg2.approx.f32 %0, %1;" : "=f"(y) : "f"(x)); return y;
}
__device__ __forceinline__ uint32_t pack_bf16x2(float lo, float hi) {
    uint32_t r;
    asm("cvt.rn.bf16x2.f32 %0, %1, %2;" : "=r"(r) : "f"(hi), "f"(lo));
    return r;
}
__device__ __forceinline__ void mma_bf16(float& d0, float& d1, float& d2, float& d3,
                                         uint32_t a0, uint32_t a1, uint32_t a2, uint32_t a3,
                                         uint32_t b0, uint32_t b1) {
    asm("mma.sync.aligned.m16n8k16.row.col.f32.bf16.bf16.f32 "
        "{%0,%1,%2,%3}, {%4,%5,%6,%7}, {%8,%9}, {%0,%1,%2,%3};"
        : "+f"(d0), "+f"(d1), "+f"(d2), "+f"(d3)
        : "r"(a0), "r"(a1), "r"(a2), "r"(a3), "r"(b0), "r"(b1));
}

// ---------------------------------------------------------------------------
// bf16 HMMA GEMM: C[M,N] = A[M,K=256] @ B[256,N] (+bias). Tile 64x64,
// 128 thr / 4 warps, K fully smem-resident as packed bf16x2 pairs.
// Warp w computes rows [w*16, w*16+16), all 64 n (8 n-tiles).
// ---------------------------------------------------------------------------
__global__ void __launch_bounds__(128)
gemm_hmma_kernel(const float* __restrict__ A,
                 const float* __restrict__ Bm,
                 const float* __restrict__ bias,
                 float* __restrict__ C,
                 int M, int N)
{
    extern __shared__ uint32_t gsm[];
    uint32_t* sA = gsm;                         // [64][132]  pairs {A[r][2k2],A[r][2k2+1]}
    uint32_t* sB = gsm + 64 * GASTR;            // [64][132]  pairs {B[2k2][n],B[2k2+1][n]}

    const int tid  = threadIdx.x;
    const int wid  = tid >> 5;
    const int lane = tid & 31;
    const int mb = blockIdx.y * 64;
    const int nb = blockIdx.x * 64;

    // stage A: 64 rows x 64 float4
    for (int i = tid; i < 64 * 64; i += 128) {
        int r  = i >> 6;
        int k4 = i & 63;
        int gm = mb + r;
        float4 v = make_float4(0.f, 0.f, 0.f, 0.f);
        if (gm < M) v = *(const float4*)(A + (size_t)gm * 256 + k4 * 4);
        sA[r * GASTR + k4 * 2]     = pack_bf16x2(v.x, v.y);
        sA[r * GASTR + k4 * 2 + 1] = pack_bf16x2(v.z, v.w);
    }
    // stage B: 128 k2 x 16 n4-groups
    for (int i = tid; i < 128 * 16; i += 128) {
        int k2 = i >> 4;
        int n4 = (i & 15) * 4;
        const float* p0 = Bm + (size_t)(2 * k2) * N + nb + n4;
        float4 r0 = *(const float4*)p0;
        float4 r1 = *(const float4*)(p0 + N);
        sB[(n4 + 0) * GASTR + k2] = pack_bf16x2(r0.x, r1.x);
        sB[(n4 + 1) * GASTR + k2] = pack_bf16x2(r0.y, r1.y);
        sB[(n4 + 2) * GASTR + k2] = pack_bf16x2(r0.z, r1.z);
        sB[(n4 + 3) * GASTR + k2] = pack_bf16x2(r0.w, r1.w);
    }
    __syncthreads();

    const int gr = lane >> 2;
    const int c  = lane & 3;
    const uint32_t* pa  = sA + (wid * 16 + gr) * GASTR;
    const uint32_t* pa8 = pa + 8 * GASTR;
    const uint32_t* pbn = sB + gr * GASTR;      // n offset (lane>>2) within n-tile

    float d0[8], d1[8], d2[8], d3[8];
    #pragma unroll
    for (int nt = 0; nt < 8; nt++) { d0[nt] = d1[nt] = d2[nt] = d3[nt] = 0.f; }

    #pragma unroll 4
    for (int ch = 0; ch < 16; ch++) {
        int k2b = ch * 8;
        uint32_t a0 = pa[k2b + c];
        uint32_t a1 = pa8[k2b + c];
        uint32_t a2 = pa[k2b + 4 + c];
        uint32_t a3 = pa8[k2b + 4 + c];
        #pragma unroll
        for (int nt = 0; nt < 8; nt++) {
            uint32_t b0 = pbn[nt * 8 * GASTR + k2b + c];
            uint32_t b1 = pbn[nt * 8 * GASTR + k2b + 4 + c];
            mma_bf16(d0[nt], d1[nt], d2[nt], d3[nt], a0, a1, a2, a3, b0, b1);
        }
    }

    // epilogue
    int gm0 = mb + wid * 16 + gr;
    int gm1 = gm0 + 8;
    #pragma unroll
    for (int nt = 0; nt < 8; nt++) {
        int gn = nb + nt * 8 + 2 * c;
        float bb0 = bias ? bias[gn]     : 0.f;
        float bb1 = bias ? bias[gn + 1] : 0.f;
        if (gm0 < M) *(float2*)(C + (size_t)gm0 * N + gn) = make_float2(d0[nt] + bb0, d1[nt] + bb1);
        if (gm1 < M) *(float2*)(C + (size_t)gm1 * N + gn) = make_float2(d2[nt] + bb0, d3[nt] + bb1);
    }
}

// ---------------------------------------------------------------------------
// HMMA joint kernel (unchanged from R8 — passing at rel 1.6e-4).
// ---------------------------------------------------------------------------
__global__ void __launch_bounds__(256)
joint_hmma_kernel(const float* __restrict__ Wp,
                  const float* __restrict__ bp,
                  const int*  __restrict__ targets)
{
    extern __shared__ char smraw[];
    float*    sG  = (float*)(smraw + SM_G);
    float*    sF  = (float*)(smraw + SM_F);
    uint32_t* sBf = (uint32_t*)(smraw + SM_BF);
    float*    sD  = (float*)(smraw + SM_D);
    float*    sBp = (float*)(smraw + SM_BP);

    const int b     = blockIdx.y;
    const int tbase = blockIdx.x * 8;
    const int tid   = threadIdx.x;
    const int wid   = tid >> 5;
    const int lane  = tid & 31;

    const float* Fb = g_F + (size_t)(b * T_ + tbase) * H_;
    const float* Gb = g_G + (size_t)b * U1_ * H_;

    if (tid < V_) sBp[tid] = bp[tid];

    for (int i = tid; i < 64 * (H_ / 4); i += 256) {
        int r = i >> 7;
        int cc = (i & 127) << 2;
        float4 v4 = make_float4(0.f, 0.f, 0.f, 0.f);
        if (r < U1_) v4 = *(const float4*)(Gb + (size_t)r * H_ + cc);
        *(float4*)&sG[r * GSTR + cc] = v4;
    }
    for (int i = tid; i < 8 * (H_ / 4); i += 256) {
        int r = i >> 7;
        int cc = (i & 127) << 2;
        *(float4*)&sF[r * H_ + cc] = *(const float4*)(Fb + (size_t)r * H_ + cc);
    }
    for (int i = tid; i < 32 * 4 * 32; i += 256) {
        int ch = i >> 7;
        int nt = (i >> 5) & 3;
        int l  = i & 31;
        int kA = ch * 16 + 2 * (l & 3);
        int n  = nt * 8 + (l >> 2);
        uint32_t b0 = 0, b1 = 0;
        if (n < V_) {
            b0 = pack_bf16x2(Wp[(size_t)kA * V_ + n],       Wp[(size_t)(kA + 1) * V_ + n]);
            b1 = pack_bf16x2(Wp[(size_t)(kA + 8) * V_ + n], Wp[(size_t)(kA + 9) * V_ + n]);
        }
        sBf[(size_t)i * 2 + 0] = b0;
        sBf[(size_t)i * 2 + 1] = b1;
    }
    __syncthreads();

    const int s    = wid & 3;
    const int tsub = wid >> 2;
    const int u0   = s * 16;
    const int gr    = lane >> 2;
    const int cbase = (lane & 3) * 2;

    const float* gRowA = sG + (u0 + gr) * GSTR;
    const float* gRowB = sG + (u0 + gr + 8) * GSTR;
    float* sDw = sD + wid * (16 * DSTR);

    #pragma unroll 1
    for (int it = 0; it < 4; it++) {
        const int tloc = tsub * 4 + it;
        const float* fRow = sF + tloc * H_;

        float d0[4], d1[4], d2[4], d3[4];
        #pragma unroll
        for (int nt = 0; nt < 4; nt++) { d0[nt] = d1[nt] = d2[nt] = d3[nt] = 0.f; }

        #pragma unroll 2
        for (int ch = 0; ch < 32; ch++) {
            int k = ch * 16 + cbase;
            float2 fA  = *(const float2*)(fRow  + k);
            float2 fB  = *(const float2*)(fRow  + k + 8);
            float2 gAa = *(const float2*)(gRowA + k);
            float2 gBa = *(const float2*)(gRowA + k + 8);
            float2 gAb = *(const float2*)(gRowB + k);
            float2 gBb = *(const float2*)(gRowB + k + 8);
            uint32_t a0 = pack_bf16x2(fast_tanh(fA.x + gAa.x), fast_tanh(fA.y + gAa.y));
            uint32_t a1 = pack_bf16x2(fast_tanh(fA.x + gAb.x), fast_tanh(fA.y + gAb.y));
            uint32_t a2 = pack_bf16x2(fast_tanh(fB.x + gBa.x), fast_tanh(fB.y + gBa.y));
            uint32_t a3 = pack_bf16x2(fast_tanh(fB.x + gBb.x), fast_tanh(fB.y + gBb.y));
            const uint32_t* bf = sBf + (size_t)(ch * 4) * 64 + lane * 2;
            #pragma unroll
            for (int nt = 0; nt < 4; nt++) {
                uint32_t bb0 = bf[nt * 64 + 0];
                uint32_t bb1 = bf[nt * 64 + 1];
                mma_bf16(d0[nt], d1[nt], d2[nt], d3[nt], a0, a1, a2, a3, bb0, bb1);
            }
        }

        #pragma unroll
        for (int nt = 0; nt < 4; nt++) {
            int cc = nt * 8 + cbase;
            *(float2*)&sDw[gr * DSTR + cc]       = make_float2(d0[nt], d1[nt]);
            *(float2*)&sDw[(gr + 8) * DSTR + cc] = make_float2(d2[nt], d3[nt]);
        }
        __syncwarp();

        if (lane < 16) {
            int u = u0 + lane;
            if (u < U1_) {
                int t = tbase + tloc;
                float logits[V_];
                float m = -1e30f;
                #pragma unroll
                for (int v = 0; v < V_; v++) {
                    logits[v] = sDw[lane * DSTR + v] + sBp[v];
                    m = fmaxf(m, logits[v]);
                }
                float ssum = 0.f;
                #pragma unroll
                for (int v = 0; v < V_; v++) ssum += fast_ex2((logits[v] - m) * LOG2E);
                float lse = m + fast_lg2(ssum) * LN2;

                int tgt = (u < U_) ? targets[b * U_ + u] : 0;
                float lv = logits[0];
                #pragma unroll
                for (int v = 1; v < V_; v++)
                    if (v == tgt) lv = logits[v];

                size_t idx = (size_t)(b * T_ + t) * U1_ + u;
                g_blank[idx] = logits[BLANK_] - lse;
                if (u < U_) g_lab[idx] = lv - lse;
            }
        }
        __syncwarp();
    }
}

// ---------------------------------------------------------------------------
// Forward DP: phase-split wavefront. Mid phase [64,399] is clamp-free with
// incremental offsets and one-step LDS prefetch off the serial chain.
// ---------------------------------------------------------------------------
__global__ void dp_kernel(const int* __restrict__ t_lens,
                          const int* __restrict__ u_lens,
                          float* __restrict__ out)
{
    extern __shared__ float sm[];
    float* sB = sm;
    float* sL = sm + T_ * U1_;

    int b   = blockIdx.x;
    int tid = threadIdx.x;

    const float4* srcB = (const float4*)(g_blank + (size_t)b * T_ * U1_);
    const float4* srcL = (const float4*)(g_lab   + (size_t)b * T_ * U1_);
    const int n4 = T_ * U1_ / 4;
    for (int i = tid; i < n4; i += 1024) {
        float4 vb = srcB[i];
        float4 vl = srcL[i];
        vb.x *= LOG2E; vb.y *= LOG2E; vb.z *= LOG2E; vb.w *= LOG2E;
        vl.x *= LOG2E; vl.y *= LOG2E; vl.z *= LOG2E; vl.w *= LOG2E;
        ((float4*)sB)[i] = vb;
        ((float4*)sL)[i] = vl;
    }
    __syncthreads();
    if (tid >= 32) return;

    const int lane = tid;
    const int Tl = t_lens[b], Ul = u_lens[b];
    const int dcap = (Tl - 1) + Ul;          // >= 229 always (Tl>=200, Ul>=30)
    const bool cap_lo = (Ul < 32) && (lane == Ul);
    const bool cap_hi = (Ul >= 32) && (lane == Ul - 32);

    const int u_lo = lane;
    const int u_hi = lane + 32;
    const int ulo_m1 = max(u_lo - 1, 0);
    const int uhi_c  = min(u_hi, U1_ - 1);
    const int uhi_m1 = min(u_hi - 1, U1_ - 1);

    float a_lo = (lane == 0) ? 0.f : NEGF;
    float a_hi = NEGF;
    float res  = 0.f;

    // ---- phase 1: d in [1,63], clamped, no capture (dcap >= 229) ----
    for (int d = 1; d <= 63; d++) {
        float p_lo = __shfl_up_sync(0xffffffffu, a_lo, 1);
        float p_hi = __shfl_up_sync(0xffffffffu, a_hi, 1);
        float lo31 = __shfl_sync(0xffffffffu, a_lo, 31);
        p_lo = (lane == 0) ? NEGF : p_lo;
        p_hi = (lane == 0) ? lo31 : p_hi;

        int t  = d - u_lo;
        int i1 = min(max(t - 1, 0), T_ - 1);
        int i2 = min(max(t, 0), T_ - 1);
        float v1 = a_lo + sB[i1 * U1_ + u_lo];
        float v2 = p_lo + sL[i2 * U1_ + ulo_m1];
        float mx = fmaxf(v1, v2), mn = fminf(v1, v2);
        a_lo = mx + fast_lg2(1.f + fast_ex2(mn - mx));

        int th = d - u_hi;
        int j1 = min(max(th - 1, 0), T_ - 1);
        int j2 = min(max(th, 0), T_ - 1);
        float w1 = a_hi + sB[j1 * U1_ + uhi_c];
        float w2 = p_hi + sL[j2 * U1_ + uhi_m1];
        float mxh = fmaxf(w1, w2), mnh = fminf(w1, w2);
        a_hi = mxh + fast_lg2(1.f + fast_ex2(mnh - mxh));
    }

    // ---- phase 2: d in [64,399], clamp-free, prefetched ----
    {
        int ob_lo = (63 - u_lo) * U1_ + u_lo;
        int ol_lo = (64 - u_lo) * U1_ + ulo_m1;
        int ob_hi = (63 - u_hi) * U1_ + uhi_c;
        int ol_hi = (64 - u_hi) * U1_ + uhi_m1;

        float Blo = sB[ob_lo], Llo = sL[ol_lo];
        float Bhi = sB[ob_hi], Lhi = sL[ol_hi];

        #pragma unroll 2
        for (int d = 64; d <= 399; d++) {
            ob_lo += U1_; ol_lo += U1_; ob_hi += U1_; ol_hi += U1_;
            float nBlo = sB[ob_lo];
            float nLlo = sL[ol_lo];
            float nBhi = sB[ob_hi];
            float nLhi = sL[ol_hi];

            float p_lo = __shfl_up_sync(0xffffffffu, a_lo, 1);
            float p_hi = __shfl_up_sync(0xffffffffu, a_hi, 1);
            float lo31 = __shfl_sync(0xffffffffu, a_lo, 31);
            p_lo = (lane == 0) ? NEGF : p_lo;
            p_hi = (lane == 0) ? lo31 : p_hi;

            float v1 = a_lo + Blo;
            float v2 = p_lo + Llo;
            float mx = fmaxf(v1, v2), mn = fminf(v1, v2);
            float n_lo = mx + fast_lg2(1.f + fast_ex2(mn - mx));

            float w1 = a_hi + Bhi;
            float w2 = p_hi + Lhi;
            float mxh = fmaxf(w1, w2), mnh = fminf(w1, w2);
            float n_hi = mxh + fast_lg2(1.f + fast_ex2(mnh - mxh));

            bool hit = (d == dcap);
            res = (hit && cap_lo) ? n_lo : res;
            res = (hit && cap_hi) ? n_hi : res;
            a_lo = n_lo;
            a_hi = n_hi;
            Blo = nBlo; Llo = nLlo; Bhi = nBhi; Lhi = nLhi;
        }
    }

    // ---- phase 3: d in [400,459], clamped ----
    for (int d = 400; d <= 459; d++) {
        float p_lo = __shfl_up_sync(0xffffffffu, a_lo, 1);
        float p_hi = __shfl_up_sync(0xffffffffu, a_hi, 1);
        float lo31 = __shfl_sync(0xffffffffu, a_lo, 31);
        p_lo = (lane == 0) ? NEGF : p_lo;
        p_hi = (lane == 0) ? lo31 : p_hi;

        int t  = d - u_lo;
        int i1 = min(max(t - 1, 0), T_ - 1);
        int i2 = min(max(t, 0), T_ - 1);
        float v1 = a_lo + sB[i1 * U1_ + u_lo];
        float v2 = p_lo + sL[i2 * U1_ + ulo_m1];
        float mx = fmaxf(v1, v2), mn = fminf(v1, v2);
        float n_lo = mx + fast_lg2(1.f + fast_ex2(mn - mx));

        int th = d - u_hi;
        int j1 = min(max(th - 1, 0), T_ - 1);
        int j2 = min(max(th, 0), T_ - 1);
        float w1 = a_hi + sB[j1 * U1_ + uhi_c];
        float w2 = p_hi + sL[j2 * U1_ + uhi_m1];
        float mxh = fmaxf(w1, w2), mnh = fminf(w1, w2);
        float n_hi = mxh + fast_lg2(1.f + fast_ex2(mnh - mxh));

        bool hit = (d == dcap);
        res = (hit && cap_lo) ? n_lo : res;
        res = (hit && cap_hi) ? n_hi : res;
        a_lo = n_lo;
        a_hi = n_hi;
    }

    if (cap_lo || cap_hi) {
        float blank_fin = g_blank[(size_t)b * T_ * U1_ + (size_t)(Tl - 1) * U1_ + Ul];
        out[b] = -(res * LN2 + blank_fin);
    }
}

// ---------------------------------------------------------------------------
extern "C" void kernel_launch(void* const* d_in, const int* in_sizes, int n_in,
                              void* d_out, int out_size)
{
    const float* enc     = (const float*)d_in[0];
    const float* dec     = (const float*)d_in[1];
    const float* We      = (const float*)d_in[2];
    const float* Wd      = (const float*)d_in[3];
    const float* bf      = (const float*)d_in[4];
    const float* Wp      = (const float*)d_in[5];
    const float* bp      = (const float*)d_in[6];
    const int*   targets = (const int*)d_in[7];
    const int*   t_lens  = (const int*)d_in[8];
    const int*   u_lens  = (const int*)d_in[9];
    float* out = (float*)d_out;

    float *pF = nullptr, *pG = nullptr;
    cudaGetSymbolAddress((void**)&pF, g_F);
    cudaGetSymbolAddress((void**)&pG, g_G);

    static bool attr_set = false;
    if (!attr_set) {
        cudaFuncSetAttribute(dp_kernel,
                             cudaFuncAttributeMaxDynamicSharedMemorySize, DP_SMEM);
        cudaFuncSetAttribute(joint_hmma_kernel,
                             cudaFuncAttributeMaxDynamicSharedMemorySize, JSMEM);
        cudaFuncSetAttribute(gemm_hmma_kernel,
                             cudaFuncAttributeMaxDynamicSharedMemorySize, GEMM_SMEM);
        attr_set = true;
    }

    // F = enc@We + bf : M=3200
    gemm_hmma_kernel<<<dim3(H_ / 64, (B_ * T_ + 63) / 64), 128, GEMM_SMEM>>>(
        enc, We, bf, pF, B_ * T_, H_);
    // G = dec@Wd : M=488
    gemm_hmma_kernel<<<dim3(H_ / 64, (B_ * U1_ + 63) / 64), 128, GEMM_SMEM>>>(
        dec, Wd, nullptr, pG, B_ * U1_, H_);
    joint_hmma_kernel<<<dim3(T_ / 8, B_), 256, JSMEM>>>(Wp, bp, targets);
    dp_kernel<<<B_, 1024, DP_SMEM>>>(t_lens, u_lens, out);
}